// round 12
// baseline (speedup 1.0000x reference)
#include <cuda_runtime.h>
#include <cstdint>

#define DIMN   1024
#define BSZ    4
#define LSEQ   8192
#define MROWS  (BSZ * LSEQ)          // 32768
#define GATE_ELEMS ((size_t)MROWS * DIMN)

#define NCHUNK 128
#define TCH    64                    // NCHUNK * TCH == LSEQ

// ---------------- GEMM tiling (legacy mma.sync tf32) ------------------------
#define BK       16                  // k-chunk per stage
#define NKCH     (DIMN / BK)         // 64
#define NSTAGE   3
#define A_STRIDE 20                  // floats per A smem row (16 + 4 pad)
#define B_STRIDE 136                 // floats per B smem row (128 + 8 pad)
#define A_ST_FL  (128 * A_STRIDE)    // 2560 floats / stage
#define B_ST_FL  (BK * B_STRIDE)     // 2176 floats / stage
#define STG_FL   (A_ST_FL + B_ST_FL) // 4736 floats
#define DYN_SMEM (NSTAGE * STG_FL * 4)   // 56832 B

// ---------------- scratch (device globals: allocation-free) ----------------
__device__ float g_z[(size_t)4 * MROWS * DIMN];   // ACTIVATED gates: F, I, G, O
__device__ float g_Xr[(size_t)MROWS * DIMN];      // X rounded to tf32 (RNA)
__device__ float g_Wr[(size_t)4 * DIMN * DIMN];   // W per gate, tf32-rounded (K-major)
__device__ float g_Ac[BSZ * NCHUNK * DIMN];
__device__ float g_Bc[BSZ * NCHUNK * DIMN];
__device__ float g_h0[BSZ * NCHUNK * DIMN];

// ---------------- helpers ----------------
__device__ __forceinline__ unsigned f2tf32(float f) {
    unsigned u;
    asm("cvt.rna.tf32.f32 %0, %1;" : "=r"(u) : "f"(f));
    return u;
}
__device__ __forceinline__ float sigm(float x) { return 1.0f / (1.0f + __expf(-x)); }
__device__ __forceinline__ float tanh_acc(float x) {
    x = fminf(fmaxf(x, -15.0f), 15.0f);
    float e = __expf(2.0f * x);
    return (e - 1.0f) / (e + 1.0f);
}
__device__ __forceinline__ uint32_t smem_u32(const void* p) {
    uint32_t a;
    asm("{ .reg .u64 t; cvta.to.shared.u64 t, %1; cvt.u32.u64 %0, t; }" : "=r"(a) : "l"(p));
    return a;
}
__device__ __forceinline__ void cp16(uint32_t dst, const void* src) {
    asm volatile("cp.async.cg.shared.global [%0], [%1], 16;" :: "r"(dst), "l"(src));
}
__device__ __forceinline__ void cp_commit() { asm volatile("cp.async.commit_group;" ::: "memory"); }
template <int N> __device__ __forceinline__ void cp_wait() {
    asm volatile("cp.async.wait_group %0;" :: "n"(N) : "memory");
}
__device__ __forceinline__ void mma_tf32(float c[4], const unsigned a[4], const unsigned b[2]) {
    asm volatile(
        "mma.sync.aligned.m16n8k8.row.col.f32.tf32.tf32.f32 "
        "{%0,%1,%2,%3}, {%4,%5,%6,%7}, {%8,%9}, {%0,%1,%2,%3};\n"
        : "+f"(c[0]), "+f"(c[1]), "+f"(c[2]), "+f"(c[3])
        : "r"(a[0]), "r"(a[1]), "r"(a[2]), "r"(a[3]), "r"(b[0]), "r"(b[1]));
}

// ---------------- prepass: round X to tf32 (RNA) ---------------------------
__global__ void prep_x(const float4* __restrict__ X) {
    size_t i = (size_t)blockIdx.x * 256 + threadIdx.x;
    float4 v = X[i];
    float4 o;
    o.x = __uint_as_float(f2tf32(v.x));
    o.y = __uint_as_float(f2tf32(v.y));
    o.z = __uint_as_float(f2tf32(v.z));
    o.w = __uint_as_float(f2tf32(v.w));
    ((float4*)g_Xr)[i] = o;
}

// ---------------- prepass: round W to tf32 (no transpose; stays K-major) ----
__global__ void prep_w(const float4* __restrict__ W0, const float4* __restrict__ W1,
                       const float4* __restrict__ W2, const float4* __restrict__ W3) {
    const int g = blockIdx.y;
    const float4* W = (g == 0) ? W0 : (g == 1) ? W1 : (g == 2) ? W2 : W3;
    float4* Wr = (float4*)(g_Wr + (size_t)g * DIMN * DIMN);
    size_t i = (size_t)blockIdx.x * 256 + threadIdx.x;
    float4 v = W[i];
    float4 o;
    o.x = __uint_as_float(f2tf32(v.x));
    o.y = __uint_as_float(f2tf32(v.y));
    o.z = __uint_as_float(f2tf32(v.z));
    o.w = __uint_as_float(f2tf32(v.w));
    Wr[i] = o;
}

// ---------------- GEMM + fused activation epilogue --------------------------
// grid (32, 256): x = gate(&3) * ntile(>>2) [keeps the A mtile hot in L2],
// y = mtile. 256 threads = 8 warps (2 M x 4 N), warp tile 64x32.
// 3-stage cp.async pipeline, BK=16, pre-rounded tf32 operands.
__global__ void __launch_bounds__(256, 2) gemm_gates(
    const float* __restrict__ b0, const float* __restrict__ b1,
    const float* __restrict__ b2, const float* __restrict__ b3)
{
    extern __shared__ float smem[];

    const int tid  = threadIdx.x;
    const int lane = tid & 31;
    const int wid  = tid >> 5;
    const int wm   = (wid >> 2) * 64;   // warp M offset
    const int wn   = (wid & 3) * 32;    // warp N offset
    const int gr   = lane >> 2;         // 0..7
    const int tg   = lane & 3;          // 0..3

    const int g  = blockIdx.x & 3;
    const int nb = blockIdx.x >> 2;
    const int gn = nb * 128;
    const size_t gm = (size_t)blockIdx.y * 128;

    const float* bias = (g == 0) ? b0 : (g == 1) ? b1 : (g == 2) ? b2 : b3;
    const float* A = g_Xr;                                  // [32768,1024]
    const float* B = g_Wr + (size_t)g * DIMN * DIMN;        // [1024,1024] K-major
    float* Z = g_z + (size_t)g * GATE_ELEMS;

    const uint32_t sb = smem_u32(smem);

    float acc[4][4][4];
    #pragma unroll
    for (int mt = 0; mt < 4; mt++)
        #pragma unroll
        for (int nt = 0; nt < 4; nt++)
            #pragma unroll
            for (int j = 0; j < 4; j++) acc[mt][nt][j] = 0.0f;

    // producer: stage slot <- k-chunk kc (kc in units of BK)
    auto load_stage = [&](int slot, int kc) {
        const uint32_t aB = sb + (uint32_t)(slot * STG_FL) * 4u;
        const uint32_t bB = aB + (uint32_t)A_ST_FL * 4u;
        const int k0 = kc * BK;
        // A: 128 rows x 4 segs of 16B  (512 chunks, 2 per thread)
        #pragma unroll
        for (int i = 0; i < 2; i++) {
            int ch = i * 256 + tid;
            int row = ch >> 2, seg = ch & 3;
            cp16(aB + (uint32_t)(row * A_STRIDE + seg * 4) * 4u,
                 A + (gm + row) * DIMN + k0 + seg * 4);
        }
        // B: 16 k-rows x 32 segs of 16B (512 chunks, 2 per thread)
        #pragma unroll
        for (int i = 0; i < 2; i++) {
            int ch = i * 256 + tid;
            int row = ch >> 5, seg = ch & 31;
            cp16(bB + (uint32_t)(row * B_STRIDE + seg * 4) * 4u,
                 B + (size_t)(k0 + row) * DIMN + gn + seg * 4);
        }
    };

    load_stage(0, 0); cp_commit();
    load_stage(1, 1); cp_commit();

    int slot = 0;
    for (int kc = 0; kc < NKCH; kc++) {
        cp_wait<NSTAGE - 2>();           // current stage landed
        __syncthreads();                 // also: everyone done reading stage we overwrite

        if (kc + 2 < NKCH) {
            int ns = slot + 2; if (ns >= NSTAGE) ns -= NSTAGE;
            load_stage(ns, kc + 2);
        }
        cp_commit();

        const float* As = smem + slot * STG_FL;
        const float* Bs = As + A_ST_FL;

        #pragma unroll
        for (int kk = 0; kk < 2; kk++) {
            const int k0 = kk * 8;
            unsigned af[4][4], bf[4][2];
            #pragma unroll
            for (int mt = 0; mt < 4; mt++) {
                int r = wm + mt * 16 + gr;
                af[mt][0] = __float_as_uint(As[r * A_STRIDE + k0 + tg]);
                af[mt][1] = __float_as_uint(As[(r + 8) * A_STRIDE + k0 + tg]);
                af[mt][2] = __float_as_uint(As[r * A_STRIDE + k0 + tg + 4]);
                af[mt][3] = __float_as_uint(As[(r + 8) * A_STRIDE + k0 + tg + 4]);
            }
            #pragma unroll
            for (int nt = 0; nt < 4; nt++) {
                int n = wn + nt * 8 + gr;
                bf[nt][0] = __float_as_uint(Bs[(k0 + tg) * B_STRIDE + n]);
                bf[nt][1] = __float_as_uint(Bs[(k0 + tg + 4) * B_STRIDE + n]);
            }
            #pragma unroll
            for (int mt = 0; mt < 4; mt++)
                #pragma unroll
                for (int nt = 0; nt < 4; nt++)
                    mma_tf32(acc[mt][nt], af[mt], bf[nt]);
        }
        slot++; if (slot >= NSTAGE) slot = 0;
    }

    // epilogue: bias + activation, store ACTIVATED gate
    #pragma unroll
    for (int mt = 0; mt < 4; mt++) {
        #pragma unroll
        for (int nt = 0; nt < 4; nt++) {
            int r = wm + mt * 16 + gr;
            int n = gn + wn + nt * 8 + 2 * tg;
            float bv0 = __ldg(bias + n);
            float bv1 = __ldg(bias + n + 1);
            float z00 = acc[mt][nt][0] + bv0, z01 = acc[mt][nt][1] + bv1;
            float z10 = acc[mt][nt][2] + bv0, z11 = acc[mt][nt][3] + bv1;
            float2 v0, v1;
            if (g == 1) {
                v0.x = tanh_acc(z00); v0.y = tanh_acc(z01);
                v1.x = tanh_acc(z10); v1.y = tanh_acc(z11);
            } else {
                v0.x = sigm(z00); v0.y = sigm(z01);
                v1.x = sigm(z10); v1.y = sigm(z11);
            }
            *(float2*)(Z + (gm + r) * (size_t)DIMN + n)     = v0;
            *(float2*)(Z + (gm + r + 8) * (size_t)DIMN + n) = v1;
        }
    }
}

// ---------------- scan pass 1: per-chunk (A = prod F, B = local tail) -------
__global__ void scan_reduce()
{
    const int d = blockIdx.x * 256 + threadIdx.x;
    const int c = blockIdx.y;
    const int b = blockIdx.z;
    const size_t base = ((size_t)(b * LSEQ + c * TCH)) * DIMN + d;
    const float* F = g_z + base;
    const float* I = g_z + GATE_ELEMS + base;
    const float* G = g_z + 2 * GATE_ELEMS + base;

    float a = 1.0f, bb = 0.0f;
    #pragma unroll 4
    for (int t = 0; t < TCH; t++) {
        float f  = F[t * DIMN];
        float iv = I[t * DIMN] * G[t * DIMN];
        a *= f;
        bb = fmaf(f, bb, iv);
    }
    int o = (b * NCHUNK + c) * DIMN + d;
    g_Ac[o] = a;
    g_Bc[o] = bb;
}

// ---------------- scan pass 2: sequential combine over chunks ---------------
__global__ void scan_combine(const float* __restrict__ hinit)
{
    const int b = blockIdx.x;
    const int d = threadIdx.x;
    float h = hinit[d];
    for (int c = 0; c < NCHUNK; c++) {
        int o = (b * NCHUNK + c) * DIMN + d;
        g_h0[o] = h;
        h = fmaf(g_Ac[o], h, g_Bc[o]);
    }
}

// ---------------- scan pass 3: apply with carry-in, write y -----------------
__global__ void scan_apply(float* __restrict__ Y)
{
    const int d = blockIdx.x * 256 + threadIdx.x;
    const int c = blockIdx.y;
    const int b = blockIdx.z;
    const size_t base = ((size_t)(b * LSEQ + c * TCH)) * DIMN + d;
    const float* F = g_z + base;
    const float* I = g_z + GATE_ELEMS + base;
    const float* G = g_z + 2 * GATE_ELEMS + base;
    const float* O = g_z + 3 * GATE_ELEMS + base;

    float h = g_h0[(b * NCHUNK + c) * DIMN + d];
    #pragma unroll 4
    for (int t = 0; t < TCH; t++) {
        float f  = F[t * DIMN];
        float iv = I[t * DIMN] * G[t * DIMN];
        h = fmaf(f, h, iv);
        Y[base + (size_t)t * DIMN] = tanh_acc(h) * O[t * DIMN];
    }
}

// ---------------- launch ----------------------------------------------------
extern "C" void kernel_launch(void* const* d_in, const int* in_sizes, int n_in,
                              void* d_out, int out_size)
{
    (void)in_sizes; (void)n_in; (void)out_size;
    const float* x   = (const float*)d_in[0];
    const float* Wf  = (const float*)d_in[1];
    const float* bf  = (const float*)d_in[2];
    const float* Wi  = (const float*)d_in[3];
    const float* bi  = (const float*)d_in[4];
    const float* Wig = (const float*)d_in[5];
    const float* big = (const float*)d_in[6];
    const float* Wog = (const float*)d_in[7];
    const float* bog = (const float*)d_in[8];
    const float* h0  = (const float*)d_in[9];
    float* y = (float*)d_out;

    static bool attr_done = false;
    if (!attr_done) {
        cudaFuncSetAttribute(gemm_gates, cudaFuncAttributeMaxDynamicSharedMemorySize, DYN_SMEM);
        attr_done = true;
    }

    prep_x<<<(MROWS * DIMN / 4) / 256, 256>>>((const float4*)x);
    prep_w<<<dim3((DIMN * DIMN / 4) / 256, 4), 256>>>(
        (const float4*)Wf, (const float4*)Wi, (const float4*)Wig, (const float4*)Wog);
    gemm_gates<<<dim3(32, 256), 256, DYN_SMEM>>>(bf, bi, big, bog);
    scan_reduce<<<dim3(DIMN / 256, NCHUNK, BSZ), 256>>>();
    scan_combine<<<BSZ, DIMN>>>(h0);
    scan_apply<<<dim3(DIMN / 256, NCHUNK, BSZ), 256>>>(y);
}

// round 13
// speedup vs baseline: 1.6125x; 1.6125x over previous
#include <cuda_runtime.h>
#include <cstdint>

#define DIMN   1024
#define BSZ    4
#define LSEQ   8192
#define MROWS  (BSZ * LSEQ)          // 32768
#define GATE_ELEMS ((size_t)MROWS * DIMN)

#define NCHUNK 128
#define TCH    64                    // NCHUNK * TCH == LSEQ

// ---------------- GEMM tiling (legacy mma.sync tf32) ------------------------
#define BK       32                  // k-chunk per stage (R6 cadence)
#define NKCH     (DIMN / BK)         // 32
#define NSTAGE   3
#define A_STRIDE 36                  // floats per A smem row (32 + 4 pad)
#define B_STRIDE 136                 // floats per B smem row (128 + 8 pad)
#define A_ST_FL  (128 * A_STRIDE)    // 4608 floats / stage
#define B_ST_FL  (BK * B_STRIDE)     // 4352 floats / stage
#define STG_FL   (A_ST_FL + B_ST_FL) // 8960 floats
#define DYN_SMEM (NSTAGE * STG_FL * 4)   // 107520 B

// ---------------- scratch (device globals: allocation-free) ----------------
__device__ float g_z[(size_t)4 * MROWS * DIMN];   // ACTIVATED gates: F, I, G, O
__device__ float g_Xr[(size_t)MROWS * DIMN];      // X rounded to tf32 (RNA)
__device__ float g_Wr[(size_t)4 * DIMN * DIMN];   // W per gate, tf32-rounded (K-major)
__device__ float g_Ac[BSZ * NCHUNK * DIMN];
__device__ float g_Bc[BSZ * NCHUNK * DIMN];
__device__ float g_h0[BSZ * NCHUNK * DIMN];

// ---------------- helpers ----------------
__device__ __forceinline__ unsigned f2tf32(float f) {
    unsigned u;
    asm("cvt.rna.tf32.f32 %0, %1;" : "=r"(u) : "f"(f));
    return u;
}
__device__ __forceinline__ float sigm(float x) { return 1.0f / (1.0f + __expf(-x)); }
__device__ __forceinline__ float tanh_acc(float x) {
    x = fminf(fmaxf(x, -15.0f), 15.0f);
    float e = __expf(2.0f * x);
    return (e - 1.0f) / (e + 1.0f);
}
__device__ __forceinline__ uint32_t smem_u32(const void* p) {
    uint32_t a;
    asm("{ .reg .u64 t; cvta.to.shared.u64 t, %1; cvt.u32.u64 %0, t; }" : "=r"(a) : "l"(p));
    return a;
}
__device__ __forceinline__ void cp16(uint32_t dst, const void* src) {
    asm volatile("cp.async.cg.shared.global [%0], [%1], 16;" :: "r"(dst), "l"(src));
}
__device__ __forceinline__ void cp_commit() { asm volatile("cp.async.commit_group;" ::: "memory"); }
template <int N> __device__ __forceinline__ void cp_wait() {
    asm volatile("cp.async.wait_group %0;" :: "n"(N) : "memory");
}
__device__ __forceinline__ void mma_tf32(float c[4], const unsigned a[4], const unsigned b[2]) {
    asm volatile(
        "mma.sync.aligned.m16n8k8.row.col.f32.tf32.tf32.f32 "
        "{%0,%1,%2,%3}, {%4,%5,%6,%7}, {%8,%9}, {%0,%1,%2,%3};\n"
        : "+f"(c[0]), "+f"(c[1]), "+f"(c[2]), "+f"(c[3])
        : "r"(a[0]), "r"(a[1]), "r"(a[2]), "r"(a[3]), "r"(b[0]), "r"(b[1]));
}

// ---------------- prepass: round X to tf32 (RNA) ---------------------------
__global__ void prep_x(const float4* __restrict__ X) {
    size_t i = (size_t)blockIdx.x * 256 + threadIdx.x;
    float4 v = X[i];
    float4 o;
    o.x = __uint_as_float(f2tf32(v.x));
    o.y = __uint_as_float(f2tf32(v.y));
    o.z = __uint_as_float(f2tf32(v.z));
    o.w = __uint_as_float(f2tf32(v.w));
    ((float4*)g_Xr)[i] = o;
}

// ---------------- prepass: round W to tf32 (no transpose; stays K-major) ----
__global__ void prep_w(const float4* __restrict__ W0, const float4* __restrict__ W1,
                       const float4* __restrict__ W2, const float4* __restrict__ W3) {
    const int g = blockIdx.y;
    const float4* W = (g == 0) ? W0 : (g == 1) ? W1 : (g == 2) ? W2 : W3;
    float4* Wr = (float4*)(g_Wr + (size_t)g * DIMN * DIMN);
    size_t i = (size_t)blockIdx.x * 256 + threadIdx.x;
    float4 v = W[i];
    float4 o;
    o.x = __uint_as_float(f2tf32(v.x));
    o.y = __uint_as_float(f2tf32(v.y));
    o.z = __uint_as_float(f2tf32(v.z));
    o.w = __uint_as_float(f2tf32(v.w));
    Wr[i] = o;
}

// ---------------- GEMM + fused activation epilogue --------------------------
// grid (32, 256): x = gate(&3) + ntile(>>2)*4 [A mtile hot in L2], y = mtile.
// 256 threads = 8 warps (2 M x 4 N), warp tile 64x32.
// 3-stage cp.async pipeline, BK=32 (one barrier per 64 MMAs), occ 2.
__global__ void __launch_bounds__(256, 2) gemm_gates(
    const float* __restrict__ b0, const float* __restrict__ b1,
    const float* __restrict__ b2, const float* __restrict__ b3)
{
    extern __shared__ float smem[];

    const int tid  = threadIdx.x;
    const int lane = tid & 31;
    const int wid  = tid >> 5;
    const int wm   = (wid >> 2) * 64;   // warp M offset
    const int wn   = (wid & 3) * 32;    // warp N offset
    const int gr   = lane >> 2;         // 0..7
    const int tg   = lane & 3;          // 0..3

    const int g  = blockIdx.x & 3;
    const int nb = blockIdx.x >> 2;
    const int gn = nb * 128;
    const size_t gm = (size_t)blockIdx.y * 128;

    const float* bias = (g == 0) ? b0 : (g == 1) ? b1 : (g == 2) ? b2 : b3;
    const float* A = g_Xr;                                  // [32768,1024]
    const float* B = g_Wr + (size_t)g * DIMN * DIMN;        // [1024,1024] K-major
    float* Z = g_z + (size_t)g * GATE_ELEMS;

    const uint32_t sb = smem_u32(smem);

    float acc[4][4][4];
    #pragma unroll
    for (int mt = 0; mt < 4; mt++)
        #pragma unroll
        for (int nt = 0; nt < 4; nt++)
            #pragma unroll
            for (int j = 0; j < 4; j++) acc[mt][nt][j] = 0.0f;

    // producer: stage slot <- k-chunk kc (kc in units of BK)
    auto load_stage = [&](int slot, int kc) {
        const uint32_t aB = sb + (uint32_t)(slot * STG_FL) * 4u;
        const uint32_t bB = aB + (uint32_t)A_ST_FL * 4u;
        const int k0 = kc * BK;
        // A: 128 rows x 8 segs of 16B  (1024 chunks, 4 per thread)
        #pragma unroll
        for (int i = 0; i < 4; i++) {
            int ch = i * 256 + tid;
            int row = ch >> 3, seg = ch & 7;
            cp16(aB + (uint32_t)(row * A_STRIDE + seg * 4) * 4u,
                 A + (gm + row) * DIMN + k0 + seg * 4);
        }
        // B: 32 k-rows x 32 segs of 16B (1024 chunks, 4 per thread)
        #pragma unroll
        for (int i = 0; i < 4; i++) {
            int ch = i * 256 + tid;
            int row = ch >> 5, seg = ch & 31;
            cp16(bB + (uint32_t)(row * B_STRIDE + seg * 4) * 4u,
                 B + (size_t)(k0 + row) * DIMN + gn + seg * 4);
        }
    };

    load_stage(0, 0); cp_commit();
    load_stage(1, 1); cp_commit();

    int slot = 0;
    for (int kc = 0; kc < NKCH; kc++) {
        cp_wait<NSTAGE - 2>();           // current stage landed
        __syncthreads();                 // all warps done reading the slot we refill

        if (kc + 2 < NKCH) {
            int ns = slot + 2; if (ns >= NSTAGE) ns -= NSTAGE;
            load_stage(ns, kc + 2);
        }
        cp_commit();

        const float* As = smem + slot * STG_FL;
        const float* Bs = As + A_ST_FL;

        #pragma unroll
        for (int kk = 0; kk < 4; kk++) {
            const int k0 = kk * 8;
            unsigned af[4][4], bf[4][2];
            #pragma unroll
            for (int mt = 0; mt < 4; mt++) {
                int r = wm + mt * 16 + gr;
                af[mt][0] = __float_as_uint(As[r * A_STRIDE + k0 + tg]);
                af[mt][1] = __float_as_uint(As[(r + 8) * A_STRIDE + k0 + tg]);
                af[mt][2] = __float_as_uint(As[r * A_STRIDE + k0 + tg + 4]);
                af[mt][3] = __float_as_uint(As[(r + 8) * A_STRIDE + k0 + tg + 4]);
            }
            #pragma unroll
            for (int nt = 0; nt < 4; nt++) {
                int n = wn + nt * 8 + gr;
                bf[nt][0] = __float_as_uint(Bs[(k0 + tg) * B_STRIDE + n]);
                bf[nt][1] = __float_as_uint(Bs[(k0 + tg + 4) * B_STRIDE + n]);
            }
            #pragma unroll
            for (int mt = 0; mt < 4; mt++)
                #pragma unroll
                for (int nt = 0; nt < 4; nt++)
                    mma_tf32(acc[mt][nt], af[mt], bf[nt]);
        }
        slot++; if (slot >= NSTAGE) slot = 0;
    }

    // epilogue: bias + activation, store ACTIVATED gate
    #pragma unroll
    for (int mt = 0; mt < 4; mt++) {
        #pragma unroll
        for (int nt = 0; nt < 4; nt++) {
            int r = wm + mt * 16 + gr;
            int n = gn + wn + nt * 8 + 2 * tg;
            float bv0 = __ldg(bias + n);
            float bv1 = __ldg(bias + n + 1);
            float z00 = acc[mt][nt][0] + bv0, z01 = acc[mt][nt][1] + bv1;
            float z10 = acc[mt][nt][2] + bv0, z11 = acc[mt][nt][3] + bv1;
            float2 v0, v1;
            if (g == 1) {
                v0.x = tanh_acc(z00); v0.y = tanh_acc(z01);
                v1.x = tanh_acc(z10); v1.y = tanh_acc(z11);
            } else {
                v0.x = sigm(z00); v0.y = sigm(z01);
                v1.x = sigm(z10); v1.y = sigm(z11);
            }
            *(float2*)(Z + (gm + r) * (size_t)DIMN + n)     = v0;
            *(float2*)(Z + (gm + r + 8) * (size_t)DIMN + n) = v1;
        }
    }
}

// ---------------- scan pass 1: per-chunk (A = prod F, B = local tail) -------
__global__ void scan_reduce()
{
    const int d = blockIdx.x * 256 + threadIdx.x;
    const int c = blockIdx.y;
    const int b = blockIdx.z;
    const size_t base = ((size_t)(b * LSEQ + c * TCH)) * DIMN + d;
    const float* F = g_z + base;
    const float* I = g_z + GATE_ELEMS + base;
    const float* G = g_z + 2 * GATE_ELEMS + base;

    float a = 1.0f, bb = 0.0f;
    #pragma unroll 4
    for (int t = 0; t < TCH; t++) {
        float f  = F[t * DIMN];
        float iv = I[t * DIMN] * G[t * DIMN];
        a *= f;
        bb = fmaf(f, bb, iv);
    }
    int o = (b * NCHUNK + c) * DIMN + d;
    g_Ac[o] = a;
    g_Bc[o] = bb;
}

// ---------------- scan pass 2: sequential combine over chunks ---------------
__global__ void scan_combine(const float* __restrict__ hinit)
{
    const int b = blockIdx.x;
    const int d = threadIdx.x;
    float h = hinit[d];
    for (int c = 0; c < NCHUNK; c++) {
        int o = (b * NCHUNK + c) * DIMN + d;
        g_h0[o] = h;
        h = fmaf(g_Ac[o], h, g_Bc[o]);
    }
}

// ---------------- scan pass 3: apply with carry-in, write y -----------------
__global__ void scan_apply(float* __restrict__ Y)
{
    const int d = blockIdx.x * 256 + threadIdx.x;
    const int c = blockIdx.y;
    const int b = blockIdx.z;
    const size_t base = ((size_t)(b * LSEQ + c * TCH)) * DIMN + d;
    const float* F = g_z + base;
    const float* I = g_z + GATE_ELEMS + base;
    const float* G = g_z + 2 * GATE_ELEMS + base;
    const float* O = g_z + 3 * GATE_ELEMS + base;

    float h = g_h0[(b * NCHUNK + c) * DIMN + d];
    #pragma unroll 4
    for (int t = 0; t < TCH; t++) {
        float f  = F[t * DIMN];
        float iv = I[t * DIMN] * G[t * DIMN];
        h = fmaf(f, h, iv);
        Y[base + (size_t)t * DIMN] = tanh_acc(h) * O[t * DIMN];
    }
}

// ---------------- launch ----------------------------------------------------
extern "C" void kernel_launch(void* const* d_in, const int* in_sizes, int n_in,
                              void* d_out, int out_size)
{
    (void)in_sizes; (void)n_in; (void)out_size;
    const float* x   = (const float*)d_in[0];
    const float* Wf  = (const float*)d_in[1];
    const float* bf  = (const float*)d_in[2];
    const float* Wi  = (const float*)d_in[3];
    const float* bi  = (const float*)d_in[4];
    const float* Wig = (const float*)d_in[5];
    const float* big = (const float*)d_in[6];
    const float* Wog = (const float*)d_in[7];
    const float* bog = (const float*)d_in[8];
    const float* h0  = (const float*)d_in[9];
    float* y = (float*)d_out;

    static bool attr_done = false;
    if (!attr_done) {
        cudaFuncSetAttribute(gemm_gates, cudaFuncAttributeMaxDynamicSharedMemorySize, DYN_SMEM);
        attr_done = true;
    }

    prep_x<<<(MROWS * DIMN / 4) / 256, 256>>>((const float4*)x);
    prep_w<<<dim3((DIMN * DIMN / 4) / 256, 4), 256>>>(
        (const float4*)Wf, (const float4*)Wi, (const float4*)Wig, (const float4*)Wog);
    gemm_gates<<<dim3(32, 256), 256, DYN_SMEM>>>(bf, bi, big, bog);
    scan_reduce<<<dim3(DIMN / 256, NCHUNK, BSZ), 256>>>();
    scan_combine<<<BSZ, DIMN>>>(h0);
    scan_apply<<<dim3(DIMN / 256, NCHUNK, BSZ), 256>>>(y);
}

// round 14
// speedup vs baseline: 2.5147x; 1.5595x over previous
#include <cuda_runtime.h>
#include <cuda_fp16.h>
#include <cstdint>

#define DIMN   1024
#define BSZ    4
#define LSEQ   8192
#define MROWS  (BSZ * LSEQ)          // 32768
#define GATE_ELEMS ((size_t)MROWS * DIMN)

#define NCHUNK 128
#define TCH    64                    // NCHUNK * TCH == LSEQ

// ---------------- GEMM tiling (legacy mma.sync fp16, fp32 accum) ------------
#define BK       64                  // k-chunk (halves) per stage
#define NKCH     (DIMN / BK)         // 16
#define NSTAGE   3
#define ASTR     72                  // halves per A/B smem row (64 + 8 pad -> 144B)
#define A_ST_HL  (128 * ASTR)        // 9216 halves / stage
#define B_ST_HL  (128 * ASTR)        // 9216 halves / stage
#define STG_HL   (A_ST_HL + B_ST_HL) // 18432 halves = 36864 B
#define DYN_SMEM (NSTAGE * STG_HL * 2)   // 110592 B

// ---------------- scratch (device globals: allocation-free) ----------------
__device__ float  g_z[(size_t)4 * MROWS * DIMN];   // ACTIVATED gates: F, I, G, O
__device__ __half g_X16[(size_t)MROWS * DIMN];     // X rounded to fp16 (RNE)
__device__ __half g_W16[(size_t)4 * DIMN * DIMN];  // W^T per gate: [n][k] fp16
__device__ float  g_Ac[BSZ * NCHUNK * DIMN];
__device__ float  g_Bc[BSZ * NCHUNK * DIMN];
__device__ float  g_h0[BSZ * NCHUNK * DIMN];

// ---------------- helpers ----------------
__device__ __forceinline__ float sigm(float x) { return 1.0f / (1.0f + __expf(-x)); }
__device__ __forceinline__ float tanh_acc(float x) {
    x = fminf(fmaxf(x, -15.0f), 15.0f);
    float e = __expf(2.0f * x);
    return (e - 1.0f) / (e + 1.0f);
}
__device__ __forceinline__ uint32_t smem_u32(const void* p) {
    uint32_t a;
    asm("{ .reg .u64 t; cvta.to.shared.u64 t, %1; cvt.u32.u64 %0, t; }" : "=r"(a) : "l"(p));
    return a;
}
__device__ __forceinline__ void cp16(uint32_t dst, const void* src) {
    asm volatile("cp.async.cg.shared.global [%0], [%1], 16;" :: "r"(dst), "l"(src));
}
__device__ __forceinline__ void cp_commit() { asm volatile("cp.async.commit_group;" ::: "memory"); }
template <int N> __device__ __forceinline__ void cp_wait() {
    asm volatile("cp.async.wait_group %0;" :: "n"(N) : "memory");
}
__device__ __forceinline__ void mma_f16(float c[4], const unsigned a[4], const unsigned b[2]) {
    asm volatile(
        "mma.sync.aligned.m16n8k16.row.col.f32.f16.f16.f32 "
        "{%0,%1,%2,%3}, {%4,%5,%6,%7}, {%8,%9}, {%0,%1,%2,%3};\n"
        : "+f"(c[0]), "+f"(c[1]), "+f"(c[2]), "+f"(c[3])
        : "r"(a[0]), "r"(a[1]), "r"(a[2]), "r"(a[3]), "r"(b[0]), "r"(b[1]));
}

// ---------------- prepass: round X to fp16 (RNE) ----------------------------
__global__ void prep_x(const float4* __restrict__ X) {
    size_t i = (size_t)blockIdx.x * 256 + threadIdx.x;
    float4 v = X[i];
    __half2* out = (__half2*)(g_X16 + 4 * i);
    out[0] = __floats2half2_rn(v.x, v.y);
    out[1] = __floats2half2_rn(v.z, v.w);
}

// ---------------- prepass: W^T [n][k] with fp16 rounding --------------------
__global__ void prep_w(const float* __restrict__ W0, const float* __restrict__ W1,
                       const float* __restrict__ W2, const float* __restrict__ W3) {
    __shared__ float t[32][33];
    const int g = blockIdx.z;
    const float* W = (g == 0) ? W0 : (g == 1) ? W1 : (g == 2) ? W2 : W3;
    __half* Wt = g_W16 + (size_t)g * DIMN * DIMN;
    const int n0 = blockIdx.x * 32, k0 = blockIdx.y * 32;
    const int tx = threadIdx.x, ty = threadIdx.y;   // 32 x 8
    #pragma unroll
    for (int r = 0; r < 4; r++)
        t[ty + r * 8][tx] = W[(size_t)(k0 + ty + r * 8) * DIMN + n0 + tx];
    __syncthreads();
    #pragma unroll
    for (int r = 0; r < 4; r++)
        Wt[(size_t)(n0 + ty + r * 8) * DIMN + k0 + tx] = __float2half_rn(t[tx][ty + r * 8]);
}

// ---------------- GEMM + fused activation epilogue --------------------------
// grid (32, 256): x = gate(&3) + ntile(>>2)*4 [A mtile hot in L2], y = mtile.
// 256 threads = 8 warps (2 M x 4 N), warp tile 64x32.
// fp16 mma m16n8k16, 3-stage cp.async, BK=64 (one barrier per 64 MMAs), occ 2.
__global__ void __launch_bounds__(256, 2) gemm_gates(
    const float* __restrict__ b0, const float* __restrict__ b1,
    const float* __restrict__ b2, const float* __restrict__ b3)
{
    extern __shared__ __half smem[];

    const int tid  = threadIdx.x;
    const int lane = tid & 31;
    const int wid  = tid >> 5;
    const int wm   = (wid >> 2) * 64;   // warp M offset
    const int wn   = (wid & 3) * 32;    // warp N offset
    const int gr   = lane >> 2;         // 0..7
    const int tg   = lane & 3;          // 0..3

    const int g  = blockIdx.x & 3;
    const int nb = blockIdx.x >> 2;
    const int gn = nb * 128;
    const size_t gm = (size_t)blockIdx.y * 128;

    const float* bias = (g == 0) ? b0 : (g == 1) ? b1 : (g == 2) ? b2 : b3;
    const __half* A = g_X16;                                 // [32768,1024]
    const __half* B = g_W16 + (size_t)g * DIMN * DIMN;       // [1024(n),1024(k)]
    float* Z = g_z + (size_t)g * GATE_ELEMS;

    const uint32_t sb = smem_u32(smem);

    float acc[4][4][4];
    #pragma unroll
    for (int mt = 0; mt < 4; mt++)
        #pragma unroll
        for (int nt = 0; nt < 4; nt++)
            #pragma unroll
            for (int j = 0; j < 4; j++) acc[mt][nt][j] = 0.0f;

    // producer: stage slot <- k-chunk kc (kc in units of BK halves)
    auto load_stage = [&](int slot, int kc) {
        const uint32_t aB = sb + (uint32_t)(slot * STG_HL) * 2u;
        const uint32_t bB = aB + (uint32_t)A_ST_HL * 2u;
        const int k0 = kc * BK;
        // A: 128 rows x 8 segs of 16B (8 halves) -> 1024 chunks, 4/thread
        #pragma unroll
        for (int i = 0; i < 4; i++) {
            int ch = i * 256 + tid;
            int row = ch >> 3, seg = ch & 7;
            cp16(aB + (uint32_t)(row * ASTR + seg * 8) * 2u,
                 A + (gm + row) * DIMN + k0 + seg * 8);
        }
        // B: 128 n-rows x 8 segs of 16B -> 1024 chunks, 4/thread
        #pragma unroll
        for (int i = 0; i < 4; i++) {
            int ch = i * 256 + tid;
            int row = ch >> 3, seg = ch & 7;
            cp16(bB + (uint32_t)(row * ASTR + seg * 8) * 2u,
                 B + (size_t)(gn + row) * DIMN + k0 + seg * 8);
        }
    };

    load_stage(0, 0); cp_commit();
    load_stage(1, 1); cp_commit();

    int slot = 0;
    for (int kc = 0; kc < NKCH; kc++) {
        cp_wait<NSTAGE - 2>();           // current stage landed
        __syncthreads();                 // all warps done reading the slot we refill

        if (kc + 2 < NKCH) {
            int ns = slot + 2; if (ns >= NSTAGE) ns -= NSTAGE;
            load_stage(ns, kc + 2);
        }
        cp_commit();

        const __half* As = smem + slot * STG_HL;
        const __half* Bs = As + A_ST_HL;

        #pragma unroll
        for (int kk = 0; kk < 4; kk++) {
            const int kb = kk * 16;      // k16 per mma
            unsigned af[4][4], bf[4][2];
            #pragma unroll
            for (int mt = 0; mt < 4; mt++) {
                int r = wm + mt * 16 + gr;
                af[mt][0] = *(const unsigned*)&As[r * ASTR + kb + 2 * tg];
                af[mt][1] = *(const unsigned*)&As[(r + 8) * ASTR + kb + 2 * tg];
                af[mt][2] = *(const unsigned*)&As[r * ASTR + kb + 2 * tg + 8];
                af[mt][3] = *(const unsigned*)&As[(r + 8) * ASTR + kb + 2 * tg + 8];
            }
            #pragma unroll
            for (int nt = 0; nt < 4; nt++) {
                int n = wn + nt * 8 + gr;
                bf[nt][0] = *(const unsigned*)&Bs[n * ASTR + kb + 2 * tg];
                bf[nt][1] = *(const unsigned*)&Bs[n * ASTR + kb + 2 * tg + 8];
            }
            #pragma unroll
            for (int mt = 0; mt < 4; mt++)
                #pragma unroll
                for (int nt = 0; nt < 4; nt++)
                    mma_f16(acc[mt][nt], af[mt], bf[nt]);
        }
        slot++; if (slot >= NSTAGE) slot = 0;
    }

    // epilogue: bias + activation, store ACTIVATED gate (fp32)
    #pragma unroll
    for (int mt = 0; mt < 4; mt++) {
        #pragma unroll
        for (int nt = 0; nt < 4; nt++) {
            int r = wm + mt * 16 + gr;
            int n = gn + wn + nt * 8 + 2 * tg;
            float bv0 = __ldg(bias + n);
            float bv1 = __ldg(bias + n + 1);
            float z00 = acc[mt][nt][0] + bv0, z01 = acc[mt][nt][1] + bv1;
            float z10 = acc[mt][nt][2] + bv0, z11 = acc[mt][nt][3] + bv1;
            float2 v0, v1;
            if (g == 1) {
                v0.x = tanh_acc(z00); v0.y = tanh_acc(z01);
                v1.x = tanh_acc(z10); v1.y = tanh_acc(z11);
            } else {
                v0.x = sigm(z00); v0.y = sigm(z01);
                v1.x = sigm(z10); v1.y = sigm(z11);
            }
            *(float2*)(Z + (gm + r) * (size_t)DIMN + n)     = v0;
            *(float2*)(Z + (gm + r + 8) * (size_t)DIMN + n) = v1;
        }
    }
}

// ---------------- scan pass 1: per-chunk (A = prod F, B = local tail) -------
__global__ void scan_reduce()
{
    const int d = blockIdx.x * 256 + threadIdx.x;
    const int c = blockIdx.y;
    const int b = blockIdx.z;
    const size_t base = ((size_t)(b * LSEQ + c * TCH)) * DIMN + d;
    const float* F = g_z + base;
    const float* I = g_z + GATE_ELEMS + base;
    const float* G = g_z + 2 * GATE_ELEMS + base;

    float a = 1.0f, bb = 0.0f;
    #pragma unroll 4
    for (int t = 0; t < TCH; t++) {
        float f  = F[t * DIMN];
        float iv = I[t * DIMN] * G[t * DIMN];
        a *= f;
        bb = fmaf(f, bb, iv);
    }
    int o = (b * NCHUNK + c) * DIMN + d;
    g_Ac[o] = a;
    g_Bc[o] = bb;
}

// ---------------- scan pass 2: sequential combine over chunks ---------------
__global__ void scan_combine(const float* __restrict__ hinit)
{
    const int b = blockIdx.x;
    const int d = threadIdx.x;
    float h = hinit[d];
    for (int c = 0; c < NCHUNK; c++) {
        int o = (b * NCHUNK + c) * DIMN + d;
        g_h0[o] = h;
        h = fmaf(g_Ac[o], h, g_Bc[o]);
    }
}

// ---------------- scan pass 3: apply with carry-in, write y -----------------
__global__ void scan_apply(float* __restrict__ Y)
{
    const int d = blockIdx.x * 256 + threadIdx.x;
    const int c = blockIdx.y;
    const int b = blockIdx.z;
    const size_t base = ((size_t)(b * LSEQ + c * TCH)) * DIMN + d;
    const float* F = g_z + base;
    const float* I = g_z + GATE_ELEMS + base;
    const float* G = g_z + 2 * GATE_ELEMS + base;
    const float* O = g_z + 3 * GATE_ELEMS + base;

    float h = g_h0[(b * NCHUNK + c) * DIMN + d];
    #pragma unroll 4
    for (int t = 0; t < TCH; t++) {
        float f  = F[t * DIMN];
        float iv = I[t * DIMN] * G[t * DIMN];
        h = fmaf(f, h, iv);
        Y[base + (size_t)t * DIMN] = tanh_acc(h) * O[t * DIMN];
    }
}

// ---------------- launch ----------------------------------------------------
extern "C" void kernel_launch(void* const* d_in, const int* in_sizes, int n_in,
                              void* d_out, int out_size)
{
    (void)in_sizes; (void)n_in; (void)out_size;
    const float* x   = (const float*)d_in[0];
    const float* Wf  = (const float*)d_in[1];
    const float* bf  = (const float*)d_in[2];
    const float* Wi  = (const float*)d_in[3];
    const float* bi  = (const float*)d_in[4];
    const float* Wig = (const float*)d_in[5];
    const float* big = (const float*)d_in[6];
    const float* Wog = (const float*)d_in[7];
    const float* bog = (const float*)d_in[8];
    const float* h0  = (const float*)d_in[9];
    float* y = (float*)d_out;

    static bool attr_done = false;
    if (!attr_done) {
        cudaFuncSetAttribute(gemm_gates, cudaFuncAttributeMaxDynamicSharedMemorySize, DYN_SMEM);
        attr_done = true;
    }

    prep_x<<<(MROWS * DIMN / 4) / 256, 256>>>((const float4*)x);
    prep_w<<<dim3(32, 32, 4), dim3(32, 8)>>>(Wf, Wi, Wig, Wog);
    gemm_gates<<<dim3(32, 256), 256, DYN_SMEM>>>(bf, bi, big, bog);
    scan_reduce<<<dim3(DIMN / 256, NCHUNK, BSZ), 256>>>();
    scan_combine<<<BSZ, DIMN>>>(h0);
    scan_apply<<<dim3(DIMN / 256, NCHUNK, BSZ), 256>>>(y);
}